// round 1
// baseline (speedup 1.0000x reference)
#include <cuda_runtime.h>
#include <math.h>

#define B_SETS 65536
#define P      22
#define INF_   6
#define HID    64
#define OUTD   128

#define WARPS_PER_BLOCK 8
#define THREADS (WARPS_PER_BLOCK * 32)
#define GRID 592   // 4 blocks per SM on 148 SMs, single wave

__global__ __launch_bounds__(THREADS, 1)
void set_encoder_kernel(const float* __restrict__ player_locs,
                        const float* __restrict__ actor_locs,
                        const float* __restrict__ flags,
                        const int*   __restrict__ mask,
                        const float* __restrict__ W1,
                        const float* __restrict__ b1,
                        const float* __restrict__ W2,
                        const float* __restrict__ b2,
                        float*       __restrict__ out)
{
    __shared__ float  sW2[HID * OUTD];                 // 32 KB
    __shared__ float4 sf0[WARPS_PER_BLOCK][P];         // dx,dy,dist,angle
    __shared__ float2 sf1[WARPS_PER_BLOCK][P];         // teammate,keeper

    const int tid  = threadIdx.x;
    const int lane = tid & 31;
    const int wip  = tid >> 5;

    // Stage W2 into shared (vectorized, once per block)
    {
        const float4* W2v  = (const float4*)W2;
        float4*       sW2v = (float4*)sW2;
        #pragma unroll
        for (int i = tid; i < HID * OUTD / 4; i += THREADS) sW2v[i] = W2v[i];
    }

    // Per-lane W1 columns j = lane and lane+32 live in registers
    float w1a[INF_], w1b[INF_];
    #pragma unroll
    for (int i = 0; i < INF_; i++) {
        w1a[i] = W1[i * HID + lane];
        w1b[i] = W1[i * HID + lane + 32];
    }
    const float  b1a = b1[lane];
    const float  b1b = b1[lane + 32];
    const float4 b2v = ((const float4*)b2)[lane];   // outputs 4*lane..4*lane+3

    __syncthreads();

    const int warp_global = blockIdx.x * WARPS_PER_BLOCK + wip;
    const int nwarps      = GRID * WARPS_PER_BLOCK;

    for (int b = warp_global; b < B_SETS; b += nwarps) {
        const float2 a = ((const float2*)actor_locs)[b];

        int valid = 0;
        if (lane < P) {
            const int idx = b * P + lane;
            const int m   = mask[idx];
            valid = (m != 0);
            if (valid) {
                const float2 pl = ((const float2*)player_locs)[idx];
                const float2 fl = ((const float2*)flags)[idx];
                const float dx   = pl.x - a.x;
                const float dy   = pl.y - a.y;
                const float dist = sqrtf(fmaf(dx, dx, dy * dy));
                const float ang  = atan2f(dy, dx);
                sf0[wip][lane] = make_float4(dx, dy, dist, ang);
                sf1[wip][lane] = fl;
            }
        }
        unsigned bal = __ballot_sync(0xffffffffu, valid);
        __syncwarp();
        const int cnt = __popc(bal);

        // ---- Stage 1: accumulate relu(feat @ W1 + b1) over valid players ----
        float ha = 0.f, hb = 0.f;
        while (bal) {
            const int p = __ffs(bal) - 1;
            bal &= bal - 1;                       // warp-uniform loop
            const float4 f0 = sf0[wip][p];        // broadcast LDS.128
            const float2 f1 = sf1[wip][p];        // broadcast LDS.64
            float va = b1a, vb = b1b;
            va = fmaf(f0.x, w1a[0], va);  vb = fmaf(f0.x, w1b[0], vb);
            va = fmaf(f0.y, w1a[1], va);  vb = fmaf(f0.y, w1b[1], vb);
            va = fmaf(f0.z, w1a[2], va);  vb = fmaf(f0.z, w1b[2], vb);
            va = fmaf(f0.w, w1a[3], va);  vb = fmaf(f0.w, w1b[3], vb);
            va = fmaf(f1.x, w1a[4], va);  vb = fmaf(f1.x, w1b[4], vb);
            va = fmaf(f1.y, w1a[5], va);  vb = fmaf(f1.y, w1b[5], vb);
            ha += fmaxf(va, 0.f);
            hb += fmaxf(vb, 0.f);
        }

        const float rc   = (cnt > 0) ? (1.0f / (float)cnt) : 0.0f;
        const float gate = (cnt > 0) ? 1.0f : 0.0f;
        ha *= rc;
        hb *= rc;

        // ---- Stage 2: pooled_h @ W2 + gate*b2 ; lane owns 4 outputs ----
        float4 acc;
        acc.x = b2v.x * gate;
        acc.y = b2v.y * gate;
        acc.z = b2v.z * gate;
        acc.w = b2v.w * gate;
        const float4* w2r = (const float4*)sW2;   // [HID][OUTD/4]
        #pragma unroll
        for (int j = 0; j < HID; j++) {
            const float hj = __shfl_sync(0xffffffffu, (j < 32) ? ha : hb, j & 31);
            const float4 w = w2r[j * (OUTD / 4) + lane];
            acc.x = fmaf(hj, w.x, acc.x);
            acc.y = fmaf(hj, w.y, acc.y);
            acc.z = fmaf(hj, w.z, acc.z);
            acc.w = fmaf(hj, w.w, acc.w);
        }
        ((float4*)out)[b * (OUTD / 4) + lane] = acc;
    }
}

extern "C" void kernel_launch(void* const* d_in, const int* in_sizes, int n_in,
                              void* d_out, int out_size)
{
    const float* player_locs = (const float*)d_in[0];
    const float* actor_locs  = (const float*)d_in[1];
    const float* flags       = (const float*)d_in[2];
    const int*   mask        = (const int*)  d_in[3];
    const float* W1          = (const float*)d_in[4];
    const float* b1          = (const float*)d_in[5];
    const float* W2          = (const float*)d_in[6];
    const float* b2          = (const float*)d_in[7];
    float*       out         = (float*)d_out;

    set_encoder_kernel<<<GRID, THREADS>>>(player_locs, actor_locs, flags, mask,
                                          W1, b1, W2, b2, out);
}

// round 4
// speedup vs baseline: 1.4223x; 1.4223x over previous
#include <cuda_runtime.h>
#include <math.h>

#define B_SETS 65536
#define P      22
#define INF_   6
#define HID    64
#define OUTD   128

#define WPB     8
#define THREADS (WPB * 32)
#define GRID    512            // 4096 warps -> exactly 4 chunks of S=4 sets each
#define S       4

__device__ __forceinline__ unsigned long long pack2(float lo, float hi) {
    unsigned long long r;
    asm("mov.b64 %0, {%1,%2};" : "=l"(r) : "f"(lo), "f"(hi));
    return r;
}
__device__ __forceinline__ void unpack2(unsigned long long v, float& lo, float& hi) {
    asm("mov.b64 {%0,%1}, %2;" : "=f"(lo), "=f"(hi) : "l"(v));
}
__device__ __forceinline__ unsigned long long fma2(unsigned long long a,
                                                   unsigned long long b,
                                                   unsigned long long c) {
    unsigned long long d;
    asm("fma.rn.f32x2 %0, %1, %2, %3;" : "=l"(d) : "l"(a), "l"(b), "l"(c));
    return d;
}

__global__ __launch_bounds__(THREADS, 3)
void set_encoder_kernel(const float* __restrict__ player_locs,
                        const float* __restrict__ actor_locs,
                        const float* __restrict__ flags,
                        const int*   __restrict__ mask,
                        const float* __restrict__ W1,
                        const float* __restrict__ b1,
                        const float* __restrict__ W2,
                        const float* __restrict__ b2,
                        float*       __restrict__ out)
{
    __shared__ float  sW2[HID * OUTD];            // 32 KB, read via per-lane LDS.128
    __shared__ float  shh[WPB][HID][S];           // pooled hidden, 4 sets per warp
    __shared__ float4 sf0[WPB][P];                // dx,dy,dist,angle
    __shared__ float2 sf1[WPB][P];                // teammate,keeper

    const int tid  = threadIdx.x;
    const int lane = tid & 31;
    const int wip  = tid >> 5;

    {   // stage W2 into shared once per block
        const float4* W2v  = (const float4*)W2;
        float4*       sW2v = (float4*)sW2;
        #pragma unroll
        for (int i = tid; i < HID * OUTD / 4; i += THREADS) sW2v[i] = W2v[i];
    }

    // W1 columns (lane, lane+32) in registers
    float w1a[INF_], w1b[INF_];
    #pragma unroll
    for (int i = 0; i < INF_; i++) {
        w1a[i] = W1[i * HID + lane];
        w1b[i] = W1[i * HID + lane + 32];
    }
    const float b1a = b1[lane];
    const float b1b = b1[lane + 32];
    float bv[4];
    {   const float4 t = ((const float4*)b2)[lane];
        bv[0] = t.x; bv[1] = t.y; bv[2] = t.z; bv[3] = t.w; }

    __syncthreads();

    const int warp_global = blockIdx.x * WPB + wip;
    const int nwarps      = GRID * WPB;

    for (int b0 = warp_global * S; b0 < B_SETS; b0 += nwarps * S) {
        // ---- prefetch all 4 sets' inputs (high MLP to hide DRAM latency) ----
        int    mm[S];
        float2 pl[S], fl[S], aa[S];
        #pragma unroll
        for (int s = 0; s < S; s++) {
            aa[s] = ((const float2*)actor_locs)[b0 + s];
            if (lane < P) {
                const int idx = (b0 + s) * P + lane;
                mm[s] = mask[idx];
                pl[s] = ((const float2*)player_locs)[idx];
                fl[s] = ((const float2*)flags)[idx];
            }
        }

        float gate[S];

        // ---- per set: features + stage 1 (masked sum of relu(f@W1+b1)) ----
        #pragma unroll
        for (int s = 0; s < S; s++) {
            int valid = 0;
            if (lane < P) {
                valid = (mm[s] != 0);
                if (valid) {
                    const float dx   = pl[s].x - aa[s].x;
                    const float dy   = pl[s].y - aa[s].y;
                    const float dist = sqrtf(fmaf(dx, dx, dy * dy));
                    const float ang  = atan2f(dy, dx);
                    sf0[wip][lane] = make_float4(dx, dy, dist, ang);
                    sf1[wip][lane] = fl[s];
                }
            }
            unsigned bal = __ballot_sync(0xffffffffu, valid);
            __syncwarp();
            const int cnt = __popc(bal);

            float ha = 0.f, hb = 0.f;
            while (bal) {
                const int p = __ffs(bal) - 1;
                bal &= bal - 1;                       // warp-uniform
                const float4 f0 = sf0[wip][p];        // broadcast LDS.128
                const float2 f1 = sf1[wip][p];        // broadcast LDS.64
                float va = b1a, vb = b1b;
                va = fmaf(f0.x, w1a[0], va);  vb = fmaf(f0.x, w1b[0], vb);
                va = fmaf(f0.y, w1a[1], va);  vb = fmaf(f0.y, w1b[1], vb);
                va = fmaf(f0.z, w1a[2], va);  vb = fmaf(f0.z, w1b[2], vb);
                va = fmaf(f0.w, w1a[3], va);  vb = fmaf(f0.w, w1b[3], vb);
                va = fmaf(f1.x, w1a[4], va);  vb = fmaf(f1.x, w1b[4], vb);
                va = fmaf(f1.y, w1a[5], va);  vb = fmaf(f1.y, w1b[5], vb);
                ha += fmaxf(va, 0.f);
                hb += fmaxf(vb, 0.f);
            }

            const float rc = (cnt > 0) ? (1.0f / (float)cnt) : 0.0f;
            gate[s] = (cnt > 0) ? 1.0f : 0.0f;
            shh[wip][lane     ][s] = ha * rc;
            shh[wip][lane + 32][s] = hb * rc;
            __syncwarp();
        }

        // ---- stage 2: out[s] = h[s] @ W2 + gate[s]*b2, 4 sets at a time ----
        // pairs: (s0,s1) and (s2,s3) packed into f32x2 accumulators
        unsigned long long acc01[4], acc23[4];
        #pragma unroll
        for (int c = 0; c < 4; c++) {
            acc01[c] = pack2(bv[c] * gate[0], bv[c] * gate[1]);
            acc23[c] = pack2(bv[c] * gate[2], bv[c] * gate[3]);
        }

        const float4* w2r  = (const float4*)sW2;
        const float4* hrow = (const float4*)&shh[wip][0][0];
        #pragma unroll
        for (int j = 0; j < HID; j++) {
            const float4 w  = w2r[j * (OUTD / 4) + lane];  // per-lane LDS.128
            const float4 hv = hrow[j];                     // broadcast LDS.128: h_j for 4 sets
            const unsigned long long h01 = pack2(hv.x, hv.y);
            const unsigned long long h23 = pack2(hv.z, hv.w);
            const unsigned long long wd0 = pack2(w.x, w.x);
            const unsigned long long wd1 = pack2(w.y, w.y);
            const unsigned long long wd2 = pack2(w.z, w.z);
            const unsigned long long wd3 = pack2(w.w, w.w);
            acc01[0] = fma2(h01, wd0, acc01[0]);  acc23[0] = fma2(h23, wd0, acc23[0]);
            acc01[1] = fma2(h01, wd1, acc01[1]);  acc23[1] = fma2(h23, wd1, acc23[1]);
            acc01[2] = fma2(h01, wd2, acc01[2]);  acc23[2] = fma2(h23, wd2, acc23[2]);
            acc01[3] = fma2(h01, wd3, acc01[3]);  acc23[3] = fma2(h23, wd3, acc23[3]);
        }

        // ---- unpack and store: one STG.128 per set ----
        float4 o0, o1, o2, o3;
        unpack2(acc01[0], o0.x, o1.x);  unpack2(acc23[0], o2.x, o3.x);
        unpack2(acc01[1], o0.y, o1.y);  unpack2(acc23[1], o2.y, o3.y);
        unpack2(acc01[2], o0.z, o1.z);  unpack2(acc23[2], o2.z, o3.z);
        unpack2(acc01[3], o0.w, o1.w);  unpack2(acc23[3], o2.w, o3.w);
        float4* ov = (float4*)out;
        ov[(b0 + 0) * (OUTD / 4) + lane] = o0;
        ov[(b0 + 1) * (OUTD / 4) + lane] = o1;
        ov[(b0 + 2) * (OUTD / 4) + lane] = o2;
        ov[(b0 + 3) * (OUTD / 4) + lane] = o3;
    }
}

extern "C" void kernel_launch(void* const* d_in, const int* in_sizes, int n_in,
                              void* d_out, int out_size)
{
    const float* player_locs = (const float*)d_in[0];
    const float* actor_locs  = (const float*)d_in[1];
    const float* flags       = (const float*)d_in[2];
    const int*   mask        = (const int*)  d_in[3];
    const float* W1          = (const float*)d_in[4];
    const float* b1          = (const float*)d_in[5];
    const float* W2          = (const float*)d_in[6];
    const float* b2          = (const float*)d_in[7];
    float*       out         = (float*)d_out;

    set_encoder_kernel<<<GRID, THREADS>>>(player_locs, actor_locs, flags, mask,
                                          W1, b1, W2, b2, out);
}

// round 9
// speedup vs baseline: 1.6363x; 1.1505x over previous
#include <cuda_runtime.h>
#include <math.h>

#define B_SETS 65536
#define P      22
#define INF_   6
#define HID    64
#define OUTD   128

#define WPB     8
#define THREADS (WPB * 32)
#define GRID    592                 // 148 SMs * 4 blocks/SM, perfectly even residency
#define S       4
#define NCHUNKS (B_SETS / S)        // 16384
#define NWARPS  (GRID * WPB)        // 4736

__device__ __forceinline__ unsigned long long pack2(float lo, float hi) {
    unsigned long long r;
    asm("mov.b64 %0, {%1,%2};" : "=l"(r) : "f"(lo), "f"(hi));
    return r;
}
__device__ __forceinline__ void unpack2(unsigned long long v, float& lo, float& hi) {
    asm("mov.b64 {%0,%1}, %2;" : "=f"(lo), "=f"(hi) : "l"(v));
}
__device__ __forceinline__ unsigned long long fma2(unsigned long long a,
                                                   unsigned long long b,
                                                   unsigned long long c) {
    unsigned long long d;
    asm("fma.rn.f32x2 %0, %1, %2, %3;" : "=l"(d) : "l"(a), "l"(b), "l"(c));
    return d;
}

// fast atan2: minimax deg-11 odd poly on [0,1], abs err ~1e-6 (output tol 1e-3)
__device__ __forceinline__ float fast_atan2(float y, float x) {
    const float ax = fabsf(x), ay = fabsf(y);
    const float mx = fmaxf(ax, ay), mn = fminf(ax, ay);
    float t = (mx > 0.f) ? __fdividef(mn, mx) : 0.f;
    const float a = t * t;
    float p = fmaf(a, -0.01172120f, 0.05265332f);
    p = fmaf(a, p, -0.11643287f);
    p = fmaf(a, p,  0.19354346f);
    p = fmaf(a, p, -0.33262347f);
    p = fmaf(a, p,  0.99997726f);
    float r = t * p;
    if (ay > ax)  r = 1.57079632679f - r;
    if (x < 0.f)  r = 3.14159265359f - r;
    return (y < 0.f) ? -r : r;
}

__global__ __launch_bounds__(THREADS, 4)
void set_encoder_kernel(const float* __restrict__ player_locs,
                        const float* __restrict__ actor_locs,
                        const float* __restrict__ flags,
                        const int*   __restrict__ mask,
                        const float* __restrict__ W1,
                        const float* __restrict__ b1,
                        const float* __restrict__ W2,
                        const float* __restrict__ b2,
                        float*       __restrict__ out)
{
    __shared__ float  sW2[HID * OUTD];            // 32 KB
    __shared__ float  shh[WPB][HID][S];           // pooled hidden per warp
    __shared__ float4 sf0[WPB][P];                // dx,dy,dist,angle
    __shared__ float2 sf1[WPB][P];                // teammate,keeper

    const int tid  = threadIdx.x;
    const int lane = tid & 31;
    const int wip  = tid >> 5;

    {   // stage W2 into shared once per block
        const float4* W2v  = (const float4*)W2;
        float4*       sW2v = (float4*)sW2;
        #pragma unroll
        for (int i = tid; i < HID * OUTD / 4; i += THREADS) sW2v[i] = W2v[i];
    }

    // W1 columns (lane, lane+32) in registers
    float w1a[INF_], w1b[INF_];
    #pragma unroll
    for (int i = 0; i < INF_; i++) {
        w1a[i] = W1[i * HID + lane];
        w1b[i] = W1[i * HID + lane + 32];
    }
    const float b1a = b1[lane];
    const float b1b = b1[lane + 32];
    float bv[4];
    {   const float4 t = ((const float4*)b2)[lane];
        bv[0] = t.x; bv[1] = t.y; bv[2] = t.z; bv[3] = t.w; }

    __syncthreads();

    const int warp_global = blockIdx.x * WPB + wip;

    for (int chunk = warp_global; chunk < NCHUNKS; chunk += NWARPS) {
        const int b0 = chunk * S;
        float gate[S];

        // ---- per set: load, features, stage 1 (masked sum of relu(f@W1+b1)) ----
        #pragma unroll
        for (int s = 0; s < S; s++) {
            const int bset = b0 + s;
            int valid = 0;
            if (lane < P) {
                const int idx = bset * P + lane;
                valid = (mask[idx] != 0);
                if (valid) {
                    const float2 a  = ((const float2*)actor_locs)[bset];
                    const float2 pl = ((const float2*)player_locs)[idx];
                    const float2 fl = ((const float2*)flags)[idx];
                    const float dx   = pl.x - a.x;
                    const float dy   = pl.y - a.y;
                    const float dist = sqrtf(fmaf(dx, dx, dy * dy));
                    const float ang  = fast_atan2(dy, dx);
                    sf0[wip][lane] = make_float4(dx, dy, dist, ang);
                    sf1[wip][lane] = fl;
                }
            }
            unsigned bal = __ballot_sync(0xffffffffu, valid);
            __syncwarp();
            const int cnt = __popc(bal);

            float ha = 0.f, hb = 0.f;
            while (bal) {
                const int p = __ffs(bal) - 1;
                bal &= bal - 1;                       // warp-uniform
                const float4 f0 = sf0[wip][p];        // broadcast LDS.128
                const float2 f1 = sf1[wip][p];        // broadcast LDS.64
                float va = b1a, vb = b1b;
                va = fmaf(f0.x, w1a[0], va);  vb = fmaf(f0.x, w1b[0], vb);
                va = fmaf(f0.y, w1a[1], va);  vb = fmaf(f0.y, w1b[1], vb);
                va = fmaf(f0.z, w1a[2], va);  vb = fmaf(f0.z, w1b[2], vb);
                va = fmaf(f0.w, w1a[3], va);  vb = fmaf(f0.w, w1b[3], vb);
                va = fmaf(f1.x, w1a[4], va);  vb = fmaf(f1.x, w1b[4], vb);
                va = fmaf(f1.y, w1a[5], va);  vb = fmaf(f1.y, w1b[5], vb);
                ha += fmaxf(va, 0.f);
                hb += fmaxf(vb, 0.f);
            }

            const float rc = (cnt > 0) ? (1.0f / (float)cnt) : 0.0f;
            gate[s] = (cnt > 0) ? 1.0f : 0.0f;
            shh[wip][lane     ][s] = ha * rc;
            shh[wip][lane + 32][s] = hb * rc;
            __syncwarp();
        }

        // ---- stage 2: out[s] = h[s] @ W2 + gate[s]*b2, 4 sets at a time ----
        unsigned long long acc01[4], acc23[4];
        #pragma unroll
        for (int c = 0; c < 4; c++) {
            acc01[c] = pack2(bv[c] * gate[0], bv[c] * gate[1]);
            acc23[c] = pack2(bv[c] * gate[2], bv[c] * gate[3]);
        }

        const float4* w2r  = (const float4*)sW2;
        const float4* hrow = (const float4*)&shh[wip][0][0];
        #pragma unroll
        for (int j = 0; j < HID; j++) {
            const float4 w  = w2r[j * (OUTD / 4) + lane];  // per-lane LDS.128
            const float4 hv = hrow[j];                     // broadcast: h_j, 4 sets
            const unsigned long long h01 = pack2(hv.x, hv.y);
            const unsigned long long h23 = pack2(hv.z, hv.w);
            const unsigned long long wd0 = pack2(w.x, w.x);
            const unsigned long long wd1 = pack2(w.y, w.y);
            const unsigned long long wd2 = pack2(w.z, w.z);
            const unsigned long long wd3 = pack2(w.w, w.w);
            acc01[0] = fma2(h01, wd0, acc01[0]);  acc23[0] = fma2(h23, wd0, acc23[0]);
            acc01[1] = fma2(h01, wd1, acc01[1]);  acc23[1] = fma2(h23, wd1, acc23[1]);
            acc01[2] = fma2(h01, wd2, acc01[2]);  acc23[2] = fma2(h23, wd2, acc23[2]);
            acc01[3] = fma2(h01, wd3, acc01[3]);  acc23[3] = fma2(h23, wd3, acc23[3]);
        }

        float4 o0, o1, o2, o3;
        unpack2(acc01[0], o0.x, o1.x);  unpack2(acc23[0], o2.x, o3.x);
        unpack2(acc01[1], o0.y, o1.y);  unpack2(acc23[1], o2.y, o3.y);
        unpack2(acc01[2], o0.z, o1.z);  unpack2(acc23[2], o2.z, o3.z);
        unpack2(acc01[3], o0.w, o1.w);  unpack2(acc23[3], o2.w, o3.w);
        float4* ov = (float4*)out;
        ov[(b0 + 0) * (OUTD / 4) + lane] = o0;
        ov[(b0 + 1) * (OUTD / 4) + lane] = o1;
        ov[(b0 + 2) * (OUTD / 4) + lane] = o2;
        ov[(b0 + 3) * (OUTD / 4) + lane] = o3;
    }
}

extern "C" void kernel_launch(void* const* d_in, const int* in_sizes, int n_in,
                              void* d_out, int out_size)
{
    const float* player_locs = (const float*)d_in[0];
    const float* actor_locs  = (const float*)d_in[1];
    const float* flags       = (const float*)d_in[2];
    const int*   mask        = (const int*)  d_in[3];
    const float* W1          = (const float*)d_in[4];
    const float* b1          = (const float*)d_in[5];
    const float* W2          = (const float*)d_in[6];
    const float* b2          = (const float*)d_in[7];
    float*       out         = (float*)d_out;

    set_encoder_kernel<<<GRID, THREADS>>>(player_locs, actor_locs, flags, mask,
                                          W1, b1, W2, b2, out);
}